// round 15
// baseline (speedup 1.0000x reference)
#include <cuda_runtime.h>
#include <cuda_bf16.h>

#define SLEN 256
#define BSZ 8
#define NH 16
#define DH 64
#define IND 1024
#define ROWS (SLEN*BSZ) /* 2048 */
#define NPAIR 128
#define NWORK 20
#define NCTA (NPAIR + NWORK)     /* 148 */
#define NTILE 256                /* 32 m-groups x 8 n-tiles (64x128 tiles) */

typedef unsigned long long ull;
typedef unsigned int uint32;

// ---- scratch (no allocs allowed -> device globals) ----
__device__ unsigned short g_ys_hi[ROWS * IND];  // scan outputs, bf16 hi (4MB)
__device__ unsigned short g_ys_lo[ROWS * IND];  // bf16 lo of residual (4MB)
__device__ unsigned short g_whi[IND * IND];     // out_w bf16 hi (2MB)
__device__ unsigned short g_wlo[IND * IND];     // out_w bf16 lo (2MB)
__device__ float g_mu[ROWS];
__device__ float g_rs[ROWS];
// pool coordination (zeroed by reset kernel each launch)
__device__ int g_ticket;
__device__ int g_prog8[32];     // per 8-step scan progress, target 128

// ---- f32x2 helpers (sm_103a packed fp32 math, PTX-only) ----
__device__ __forceinline__ ull pack2(float lo, float hi) {
    ull r;
    asm("mov.b64 %0, {%1,%2};" : "=l"(r) : "f"(lo), "f"(hi));
    return r;
}
__device__ __forceinline__ void unpack2(ull v, float& lo, float& hi) {
    asm("mov.b64 {%0,%1}, %2;" : "=f"(lo), "=f"(hi) : "l"(v));
}
__device__ __forceinline__ ull ffma2(ull a, ull b, ull c) {
    ull d;
    asm("fma.rn.f32x2 %0, %1, %2, %3;" : "=l"(d) : "l"(a), "l"(b), "l"(c));
    return d;
}
__device__ __forceinline__ ull fmul2(ull a, ull b) {
    ull d;
    asm("mul.rn.f32x2 %0, %1, %2;" : "=l"(d) : "l"(a), "l"(b));
    return d;
}
__device__ __forceinline__ ull fadd2(ull a, ull b) {
    ull d;
    asm("add.rn.f32x2 %0, %1, %2;" : "=l"(d) : "l"(a), "l"(b));
    return d;
}
__device__ __forceinline__ float warp_sum(float v) {
    #pragma unroll
    for (int o = 16; o; o >>= 1) v += __shfl_xor_sync(0xffffffffu, v, o);
    return v;
}
__device__ __forceinline__ void split_bf16(float v, unsigned short& hi, unsigned short& lo) {
    __nv_bfloat16 hb = __float2bfloat16_rn(v);
    float rem = v - __bfloat162float(hb);
    hi = __bfloat16_as_ushort(hb);
    lo = __bfloat16_as_ushort(__float2bfloat16_rn(rem));
}
__device__ __forceinline__ uint32 smaddr(const void* p) {
    return (uint32)__cvta_generic_to_shared(p);
}
__device__ __forceinline__ void ldmx4(uint32* r, uint32 a) {
    asm volatile("ldmatrix.sync.aligned.m8n8.x4.shared.b16 {%0,%1,%2,%3},[%4];"
                 : "=r"(r[0]), "=r"(r[1]), "=r"(r[2]), "=r"(r[3]) : "r"(a));
}
__device__ __forceinline__ void mma16816(float* d, const uint32* a, uint32 b0, uint32 b1) {
    asm volatile(
        "mma.sync.aligned.m16n8k16.row.col.f32.bf16.bf16.f32 "
        "{%0,%1,%2,%3},{%4,%5,%6,%7},{%8,%9},{%0,%1,%2,%3};"
        : "+f"(d[0]), "+f"(d[1]), "+f"(d[2]), "+f"(d[3])
        : "r"(a[0]), "r"(a[1]), "r"(a[2]), "r"(a[3]), "r"(b0), "r"(b1));
}

// ============================================================
// Kernel R: reset pool counters (runs first every launch; makes
// graph replays self-consistent).
// ============================================================
__global__ void reset_kernel() {
    if (threadIdx.x == 0) g_ticket = 0;
    if (threadIdx.x < 32) g_prog8[threadIdx.x] = 0;
}

// ============================================================
// Kernel 0: split out_w into bf16 hi/lo (full grid, 5us,
// stream-ordered before the fused kernel).
// ============================================================
__global__ __launch_bounds__(256) void wconv_kernel(const float* __restrict__ W) {
    int idx = (blockIdx.x * 256 + threadIdx.x) * 4;
    float4 v = *(const float4*)(W + idx);
    unsigned short h0, l0, h1, l1, h2, l2, h3, l3;
    split_bf16(v.x, h0, l0); split_bf16(v.y, h1, l1);
    split_bf16(v.z, h2, l2); split_bf16(v.w, h3, l3);
    uint2 hv, lv;
    hv.x = (uint32)h0 | ((uint32)h1 << 16); hv.y = (uint32)h2 | ((uint32)h3 << 16);
    lv.x = (uint32)l0 | ((uint32)l1 << 16); lv.y = (uint32)l2 | ((uint32)l3 << 16);
    *(uint2*)(g_whi + idx) = hv;
    *(uint2*)(g_wlo + idx) = lv;
}

// ============================================================
// GEMM tile worker: 64x128 tile, 128 threads (4 warps of 32x64),
// bf16-split tensor cores (Ahi*Bhi + Ahi*Blo + Alo*Bhi).
// Single-buffered smem (R8-proven pattern), 2 barriers per kt.
// ============================================================
struct GemmSmem {
    unsigned short Ahi[64 * 40];
    unsigned short Alo[64 * 40];
    unsigned short Bhi[128 * 40];
    unsigned short Blo[128 * 40];
};

__device__ void gemm_tile(GemmSmem* sm, int m0, int n0,
                          const float* __restrict__ h,
                          const float* __restrict__ gamma,
                          const float* __restrict__ lbeta,
                          float* __restrict__ out)
{
    const int tid  = threadIdx.x;
    const int warp = tid >> 5, lane = tid & 31;
    const int wm = (warp >> 1) * 32, wn = (warp & 1) * 64;

    // staging: A rows 0..63 (2 threads/row), B rows 0..127 (1 thread/row)
    const int arow = tid >> 1, akg = (tid & 1) * 16;
    const int brow = tid;

    float acc[2][8][4];
    #pragma unroll
    for (int i = 0; i < 2; i++)
        #pragma unroll
        for (int j = 0; j < 8; j++)
            #pragma unroll
            for (int k = 0; k < 4; k++) acc[i][j][k] = 0.f;

    const unsigned short* Ah = g_ys_hi + (size_t)(m0 + arow) * IND + akg;
    const unsigned short* Al = g_ys_lo + (size_t)(m0 + arow) * IND + akg;
    const unsigned short* Bh = g_whi   + (size_t)(n0 + brow) * IND;
    const unsigned short* Bl = g_wlo   + (size_t)(n0 + brow) * IND;

    uint4 vah0 = *(const uint4*)(Ah),     vah1 = *(const uint4*)(Ah + 8);
    uint4 val0 = *(const uint4*)(Al),     val1 = *(const uint4*)(Al + 8);
    uint4 vbh[4], vbl[4];
    #pragma unroll
    for (int i = 0; i < 4; i++) {
        vbh[i] = *(const uint4*)(Bh + i * 8);
        vbl[i] = *(const uint4*)(Bl + i * 8);
    }

    const int lr = lane & 15, lc = lane >> 4;
    const uint32 aHiB = smaddr(sm->Ahi), aLoB = smaddr(sm->Alo);
    const uint32 bHiB = smaddr(sm->Bhi), bLoB = smaddr(sm->Blo);
    const int stsA = arow * 40 + akg;
    const int stsB = brow * 40;

    for (int kt = 0; kt < IND / 32; ++kt) {
        __syncthreads();   // previous tile contents consumed
        *(uint4*)(sm->Ahi + stsA) = vah0;  *(uint4*)(sm->Ahi + stsA + 8) = vah1;
        *(uint4*)(sm->Alo + stsA) = val0;  *(uint4*)(sm->Alo + stsA + 8) = val1;
        #pragma unroll
        for (int i = 0; i < 4; i++) {
            *(uint4*)(sm->Bhi + stsB + i * 8) = vbh[i];
            *(uint4*)(sm->Blo + stsB + i * 8) = vbl[i];
        }
        __syncthreads();
        if (kt + 1 < IND / 32) {
            const int o = (kt + 1) * 32;
            vah0 = *(const uint4*)(Ah + o); vah1 = *(const uint4*)(Ah + o + 8);
            val0 = *(const uint4*)(Al + o); val1 = *(const uint4*)(Al + o + 8);
            #pragma unroll
            for (int i = 0; i < 4; i++) {
                vbh[i] = *(const uint4*)(Bh + o + i * 8);
                vbl[i] = *(const uint4*)(Bl + o + i * 8);
            }
        }
        #pragma unroll
        for (int ks = 0; ks < 2; ks++) {
            const int kb = ks * 32 + lc * 16;
            uint32 aH[2][4], aL[2][4];
            #pragma unroll
            for (int mt = 0; mt < 2; mt++) {
                uint32 off = (uint32)(wm + mt * 16 + lr) * 80u + kb;
                ldmx4(aH[mt], aHiB + off);
                ldmx4(aL[mt], aLoB + off);
            }
            uint32 bH[4][4], bL[4][4];
            #pragma unroll
            for (int nc = 0; nc < 4; nc++) {
                uint32 off = (uint32)(wn + nc * 16 + lr) * 80u + kb;
                ldmx4(bH[nc], bHiB + off);   // [n][k] row-major == col-major kxn
                ldmx4(bL[nc], bLoB + off);
            }
            #pragma unroll
            for (int mt = 0; mt < 2; mt++)
                #pragma unroll
                for (int nc = 0; nc < 4; nc++)
                    #pragma unroll
                    for (int hn = 0; hn < 2; hn++) {
                        float* d = acc[mt][nc * 2 + hn];
                        mma16816(d, aH[mt], bH[nc][hn], bH[nc][hn + 2]);
                        mma16816(d, aH[mt], bL[nc][hn], bL[nc][hn + 2]);
                        mma16816(d, aL[mt], bH[nc][hn], bH[nc][hn + 2]);
                    }
        }
    }

    // epilogue: out = acc + (h - mu) * rsig * gamma + beta
    const int gq = lane >> 2, q = lane & 3;
    #pragma unroll
    for (int mt = 0; mt < 2; mt++) {
        int m1 = m0 + wm + mt * 16 + gq;
        int m2 = m1 + 8;
        float mu1 = g_mu[m1], rs1 = g_rs[m1];
        float mu2 = g_mu[m2], rs2 = g_rs[m2];
        const float* h1 = h + (size_t)m1 * IND;
        const float* h2 = h + (size_t)m2 * IND;
        float* o1 = out + (size_t)m1 * IND;
        float* o2 = out + (size_t)m2 * IND;
        #pragma unroll
        for (int nt = 0; nt < 8; nt++) {
            int n = n0 + wn + (nt >> 1) * 16 + (nt & 1) * 8 + q * 2;
            float2 gm = *(const float2*)(gamma + n);
            float2 bt = *(const float2*)(lbeta + n);
            float2 hv1 = *(const float2*)(h1 + n);
            float2 hv2 = *(const float2*)(h2 + n);
            const float* d = acc[mt][nt];
            float2 r1, r2;
            r1.x = d[0] + (hv1.x - mu1) * rs1 * gm.x + bt.x;
            r1.y = d[1] + (hv1.y - mu1) * rs1 * gm.y + bt.y;
            r2.x = d[2] + (hv2.x - mu2) * rs2 * gm.x + bt.x;
            r2.y = d[3] + (hv2.y - mu2) * rs2 * gm.y + bt.y;
            *(float2*)(o1 + n) = r1;
            *(float2*)(o2 + n) = r2;
        }
    }
}

// ============================================================
// FUSED kernel: 148 CTAs x 128 threads.
// CTAs 0-127: LN stats + R13 scan (unchanged, +progress atomics
// every 8 steps), then join the GEMM tile pool.
// CTAs 128-147: straight to the pool (overlap GEMM with scan).
// Tile readiness: tile m-group g needs g_prog8[g]==128.
// ============================================================
__global__ __launch_bounds__(128, 1) void fused_kernel(
    const float* __restrict__ h,
    const float* __restrict__ Wy0, const float* __restrict__ Wq0,
    const float* __restrict__ Wk0, const float* __restrict__ wb0,
    const float* __restrict__ gamma, const float* __restrict__ lbeta,
    float* __restrict__ out)
{
    __shared__ __align__(16) GemmSmem gsm;         // 30 KB (pool phase)
    __shared__ __align__(16) float xs[2][64];
    __shared__ __align__(16) float eqs[2][64], eks[2][64];
    __shared__ __align__(16) float beta_s[2][4];
    __shared__ int s_tau;

    const int tid  = threadIdx.x;
    const int pair = blockIdx.x;

    if (pair < NPAIR) {
        // =================== SCAN ROLE (R13 body) ===================
        const int b  = pair >> 4;
        const int hd = pair & 15;
        const int r    = tid >> 1;
        const int hf   = tid & 1;
        const int cb   = hf * 32;
        const int lane = tid & 31;
        const int warp = tid >> 5;

        // ---------- fused LayerNorm stats: 16 rows per CTA ----------
        #pragma unroll
        for (int rr = 0; rr < 4; rr++) {
            int row = pair * 16 + warp * 4 + rr;
            const float* p = h + (size_t)row * IND + lane * 4;
            float s = 0.f, s2 = 0.f;
            #pragma unroll
            for (int i = 0; i < 8; i++) {
                float4 v = *(const float4*)(p + i * 128);
                s += (v.x + v.y) + (v.z + v.w);
                s2 = fmaf(v.x, v.x, s2); s2 = fmaf(v.y, v.y, s2);
                s2 = fmaf(v.z, v.z, s2); s2 = fmaf(v.w, v.w, s2);
            }
            s  = warp_sum(s);
            s2 = warp_sum(s2);
            if (lane == 0) {
                float mu  = s * (1.f / IND);
                float var = s2 * (1.f / IND) - mu * mu;
                g_mu[row] = mu;
                g_rs[row] = rsqrtf(var + 1e-5f);
            }
        }

        ull wy2[16], wq2[16], wk2[16];
        {
            const int base = hd * 4096 + r * 64 + cb;
            const ulonglong2* py = (const ulonglong2*)(Wy0 + base);
            const ulonglong2* pq = (const ulonglong2*)(Wq0 + base);
            const ulonglong2* pk = (const ulonglong2*)(Wk0 + base);
            #pragma unroll
            for (int j = 0; j < 8; j++) {
                ulonglong2 vy = py[j]; wy2[2*j] = vy.x; wy2[2*j+1] = vy.y;
                ulonglong2 vq = pq[j]; wq2[2*j] = vq.x; wq2[2*j+1] = vq.y;
                ulonglong2 vk = pk[j]; wk2[2*j] = vk.x; wk2[2*j+1] = vk.y;
            }
        }
        ull wbr[16];
        {
            const float* wbp = wb0 + hd * 256 + warp;
            #pragma unroll
            for (int jj = 0; jj < 16; jj++)
                wbr[jj] = pack2(wbp[(cb + 2*jj) * 4], wbp[(cb + 2*jj + 1) * 4]);
        }

        const float*    hp  = h       + (size_t)b * IND + hd * 64;
        unsigned short* yhp = g_ys_hi + (size_t)b * IND + hd * 64;
        unsigned short* ylp = g_ys_lo + (size_t)b * IND + hd * 64;
        const int stride = BSZ * IND;

        if (tid < 64) xs[0][tid] = hp[tid];
        float nx = (tid < 64) ? __ldg(hp + stride + tid) : 0.f;
        __syncthreads();

        for (int t = 0; t < SLEN; ++t) {
            const int p  = t & 1;
            const int pn = p ^ 1;

            // ---------------- Phase A ----------------
            ull ayA = 0ull, ayB = 0ull, aqA = 0ull, aqB = 0ull, akA = 0ull, akB = 0ull;
            ull pbA = 0ull, pbB = 0ull;
            #pragma unroll
            for (int j = 0; j < 8; j++) {
                ull x2a = *(const ull*)&xs[p][cb + 2*j];
                ull x2b = *(const ull*)&xs[p][cb + 16 + 2*j];
                ayA = ffma2(wy2[j], x2a, ayA);  ayB = ffma2(wy2[j+8], x2b, ayB);
                aqA = ffma2(wq2[j], x2a, aqA);  aqB = ffma2(wq2[j+8], x2b, aqB);
                akA = ffma2(wk2[j], x2a, akA);  akB = ffma2(wk2[j+8], x2b, akB);
                pbA = ffma2(wbr[j], x2a, pbA);  pbB = ffma2(wbr[j+8], x2b, pbB);
            }
            ull ay = fadd2(ayA, ayB), aq = fadd2(aqA, aqB), ak = fadd2(akA, akB);
            float zy, zq, zk, hi_;
            unpack2(aq, zq, hi_); zq += hi_;
            unpack2(ak, zk, hi_); zk += hi_;
            unpack2(ay, zy, hi_); zy += hi_;
            float pb;
            unpack2(fadd2(pbA, pbB), pb, hi_); pb += hi_;
            zq += __shfl_xor_sync(0xffffffffu, zq, 1);
            zk += __shfl_xor_sync(0xffffffffu, zk, 1);
            zy += __shfl_xor_sync(0xffffffffu, zy, 1);
            pb += __shfl_xor_sync(0xffffffffu, pb, 1);

            float eq = __expf(zq), ek = __expf(zk);
            if (hf == 0) { eqs[p][r] = eq; eks[p][r] = ek; }
            if (lane == 0) beta_s[p][warp] = __fdividef(1.f, 1.f + __expf(-pb));
            if (tid < 64 && t + 1 < SLEN) xs[pn][tid] = nx;
            if (hf == 0) {
                unsigned short yh, yl;
                split_bf16(zy, yh, yl);
                yhp[(size_t)t * stride + r] = yh;
                ylp[(size_t)t * stride + r] = yl;
            }
            __syncthreads();   // single barrier per step

            // progress release: y rows of steps [8g, 8g+7] are published
            if (((t & 7) == 7) && tid == 0) {
                __threadfence();
                atomicAdd(&g_prog8[t >> 3], 1);
            }

            // ---------------- Phase B ----------------
            if (tid < 64 && t + 2 < SLEN) nx = __ldg(hp + (size_t)(t + 2) * stride + tid);

            ull eq2[16], ek2[16];
            ull sq2 = 0ull, sk2 = 0ull;
            #pragma unroll
            for (int j = 0; j < 8; j++) {
                eq2[j]   = *(const ull*)&eqs[p][cb + 2*j];
                ek2[j]   = *(const ull*)&eks[p][cb + 2*j];
                eq2[j+8] = *(const ull*)&eqs[p][cb + 16 + 2*j];
                ek2[j+8] = *(const ull*)&eks[p][cb + 16 + 2*j];
                sq2 = fadd2(sq2, fadd2(eq2[j], eq2[j+8]));
                sk2 = fadd2(sk2, fadd2(ek2[j], ek2[j+8]));
            }
            float stq, stk;
            unpack2(sq2, stq, hi_); stq += hi_;
            unpack2(sk2, stk, hi_); stk += hi_;
            stq += __shfl_xor_sync(0xffffffffu, stq, 1);
            stk += __shfl_xor_sync(0xffffffffu, stk, 1);
            float invq = __fdividef(1.f, stq);
            float invk = __fdividef(1.f, stk);
            ull invq2  = pack2(invq, invq);
            ull invk2  = pack2(invk, invk);
            ull ninvk2 = pack2(-invk, -invk);

            float be0 = beta_s[p][0], be1 = beta_s[p][1];
            float be2 = beta_s[p][2], be3 = beta_s[p][3];

            ull dyA = 0ull, dyB = 0ull, dqA = 0ull, dqB = 0ull, dkA = 0ull, dkB = 0ull;
            ull dbA = 0ull, dbB = 0ull;
            #pragma unroll
            for (int j = 0; j < 8; j++) {
                ull mka = ffma2(ek2[j],   ninvk2, fmul2(eq2[j],   invq2));
                ull mkb = ffma2(ek2[j+8], ninvk2, fmul2(eq2[j+8], invq2));
                dyA = ffma2(wy2[j], mka, dyA);  dyB = ffma2(wy2[j+8], mkb, dyB);
                dqA = ffma2(wq2[j], mka, dqA);  dqB = ffma2(wq2[j+8], mkb, dqB);
                dkA = ffma2(wk2[j], mka, dkA);  dkB = ffma2(wk2[j+8], mkb, dkB);
                dbA = ffma2(wbr[j], mka, dbA);  dbB = ffma2(wbr[j+8], mkb, dbB);
            }
            ull dy2 = fadd2(dyA, dyB), dq2 = fadd2(dqA, dqB), dk2 = fadd2(dkA, dkB);
            float dy, dq, dk, pd;
            unpack2(dy2, dy, hi_); dy += hi_;
            unpack2(dq2, dq, hi_); dq += hi_;
            unpack2(dk2, dk, hi_); dk += hi_;
            unpack2(fadd2(dbA, dbB), pd, hi_); pd += hi_;
            dy += __shfl_xor_sync(0xffffffffu, dy, 1);
            dq += __shfl_xor_sync(0xffffffffu, dq, 1);
            dk += __shfl_xor_sync(0xffffffffu, dk, 1);
            pd += __shfl_xor_sync(0xffffffffu, pd, 1);

            float a0 = be0 * dy, a1 = be1 * dq, a2 = be2 * dk, a3 = be3 * pd;
            ull a02 = pack2(a0, a0), a12 = pack2(a1, a1);
            ull a22 = pack2(a2, a2), a32 = pack2(a3, a3);
            #pragma unroll
            for (int j = 0; j < 16; j++) {
                ull kv2 = fmul2(ek2[j], invk2);
                wy2[j] = ffma2(a02, kv2, wy2[j]);
                wq2[j] = ffma2(a12, kv2, wq2[j]);
                wk2[j] = ffma2(a22, kv2, wk2[j]);
                wbr[j] = ffma2(a32, kv2, wbr[j]);
            }
        }
    }

    // =================== POOL ROLE (all CTAs) ===================
    for (;;) {
        __syncthreads();                      // smem + s_tau reuse safe
        if (tid == 0) s_tau = atomicAdd(&g_ticket, 1);
        __syncthreads();
        int tau = s_tau;
        if (tau >= NTILE) break;
        int gg = tau >> 3;                    // m-group (64 rows = 8 steps)
        int m0 = gg * 64, n0 = (tau & 7) * 128;
        if (tid == 0) {
            while (atomicAdd(&g_prog8[gg], 0) < NPAIR) __nanosleep(128);
        }
        __syncthreads();
        __threadfence();                      // acquire published ys/mu/rs
        gemm_tile(&gsm, m0, n0, h, gamma, lbeta, out);
    }
}

// ============================================================
extern "C" void kernel_launch(void* const* d_in, const int* in_sizes, int n_in,
                              void* d_out, int out_size) {
    const float* h   = (const float*)d_in[0];
    const float* Wy  = (const float*)d_in[1];
    const float* Wq  = (const float*)d_in[2];
    const float* Wk  = (const float*)d_in[3];
    const float* wb  = (const float*)d_in[4];
    const float* ow  = (const float*)d_in[5];
    const float* gam = (const float*)d_in[6];
    const float* bet = (const float*)d_in[7];
    float* out = (float*)d_out;

    reset_kernel<<<1, 32>>>();
    wconv_kernel<<<IND * IND / 1024, 256>>>(ow);
    fused_kernel<<<NCTA, 128>>>(h, Wy, Wq, Wk, wb, gam, bet, out);
}

// round 16
// speedup vs baseline: 1.2586x; 1.2586x over previous
#include <cuda_runtime.h>
#include <cuda_bf16.h>

#define SLEN 256
#define BSZ 8
#define NH 16
#define DH 64
#define IND 1024
#define ROWS (SLEN*BSZ) /* 2048 */

typedef unsigned long long ull;
typedef unsigned int uint32;

// ---- scratch (no allocs allowed -> device globals) ----
__device__ float g_ys[ROWS * IND];   // scan outputs fp32 (8MB)
__device__ float g_mu[ROWS];
__device__ float g_rs[ROWS];

// ---- f32x2 helpers (sm_103a packed fp32 math, PTX-only) ----
__device__ __forceinline__ ull pack2(float lo, float hi) {
    ull r;
    asm("mov.b64 %0, {%1,%2};" : "=l"(r) : "f"(lo), "f"(hi));
    return r;
}
__device__ __forceinline__ void unpack2(ull v, float& lo, float& hi) {
    asm("mov.b64 {%0,%1}, %2;" : "=f"(lo), "=f"(hi) : "l"(v));
}
__device__ __forceinline__ ull ffma2(ull a, ull b, ull c) {
    ull d;
    asm("fma.rn.f32x2 %0, %1, %2, %3;" : "=l"(d) : "l"(a), "l"(b), "l"(c));
    return d;
}
__device__ __forceinline__ ull fmul2(ull a, ull b) {
    ull d;
    asm("mul.rn.f32x2 %0, %1, %2;" : "=l"(d) : "l"(a), "l"(b));
    return d;
}
__device__ __forceinline__ ull fadd2(ull a, ull b) {
    ull d;
    asm("add.rn.f32x2 %0, %1, %2;" : "=l"(d) : "l"(a), "l"(b));
    return d;
}
__device__ __forceinline__ float warp_sum(float v) {
    #pragma unroll
    for (int o = 16; o; o >>= 1) v += __shfl_xor_sync(0xffffffffu, v, o);
    return v;
}
// bf16 hi/lo split
__device__ __forceinline__ void split_bf16(float v, unsigned short& hi, unsigned short& lo) {
    __nv_bfloat16 hb = __float2bfloat16_rn(v);
    float rem = v - __bfloat162float(hb);
    hi = __bfloat16_as_ushort(hb);
    lo = __bfloat16_as_ushort(__float2bfloat16_rn(rem));
}
// split a float4 pair into packed bf16x2 words
__device__ __forceinline__ void split8(const float4& a, const float4& b,
                                       uint4& h, uint4& l) {
    unsigned short hh[8], ll[8];
    split_bf16(a.x, hh[0], ll[0]); split_bf16(a.y, hh[1], ll[1]);
    split_bf16(a.z, hh[2], ll[2]); split_bf16(a.w, hh[3], ll[3]);
    split_bf16(b.x, hh[4], ll[4]); split_bf16(b.y, hh[5], ll[5]);
    split_bf16(b.z, hh[6], ll[6]); split_bf16(b.w, hh[7], ll[7]);
    h.x = (uint32)hh[0] | ((uint32)hh[1] << 16);
    h.y = (uint32)hh[2] | ((uint32)hh[3] << 16);
    h.z = (uint32)hh[4] | ((uint32)hh[5] << 16);
    h.w = (uint32)hh[6] | ((uint32)hh[7] << 16);
    l.x = (uint32)ll[0] | ((uint32)ll[1] << 16);
    l.y = (uint32)ll[2] | ((uint32)ll[3] << 16);
    l.z = (uint32)ll[4] | ((uint32)ll[5] << 16);
    l.w = (uint32)ll[6] | ((uint32)ll[7] << 16);
}
// tensor-core primitives
__device__ __forceinline__ uint32 smaddr(const void* p) {
    return (uint32)__cvta_generic_to_shared(p);
}
__device__ __forceinline__ void ldmx4(uint32* r, uint32 a) {
    asm volatile("ldmatrix.sync.aligned.m8n8.x4.shared.b16 {%0,%1,%2,%3},[%4];"
                 : "=r"(r[0]), "=r"(r[1]), "=r"(r[2]), "=r"(r[3]) : "r"(a));
}
__device__ __forceinline__ void mma16816(float* d, const uint32* a, uint32 b0, uint32 b1) {
    asm volatile(
        "mma.sync.aligned.m16n8k16.row.col.f32.bf16.bf16.f32 "
        "{%0,%1,%2,%3},{%4,%5,%6,%7},{%8,%9},{%0,%1,%2,%3};"
        : "+f"(d[0]), "+f"(d[1]), "+f"(d[2]), "+f"(d[3])
        : "r"(a[0]), "r"(a[1]), "r"(a[2]), "r"(a[3]), "r"(b0), "r"(b1));
}

// ============================================================
// Kernel 1: LN row stats (fused prologue) + SRWM sequential scan.
// R13-best structure; y written as plain fp32 (split moved into
// the GEMM staging path).
// ============================================================
__global__ __launch_bounds__(128, 1) void srwm_scan_kernel(
    const float* __restrict__ h,
    const float* __restrict__ Wy0, const float* __restrict__ Wq0,
    const float* __restrict__ Wk0, const float* __restrict__ wb0)
{
    const int pair = blockIdx.x;          // 0..127
    const int b  = pair >> 4;
    const int hd = pair & 15;
    const int tid  = threadIdx.x;
    const int r    = tid >> 1;            // row 0..63
    const int hf   = tid & 1;             // column half
    const int cb   = hf * 32;             // column base
    const int lane = tid & 31;
    const int warp = tid >> 5;            // 0..3 == beta channel c

    // ---------- fused LayerNorm stats: 16 rows per CTA ----------
    {
        #pragma unroll
        for (int rr = 0; rr < 4; rr++) {
            int row = pair * 16 + warp * 4 + rr;
            const float* p = h + (size_t)row * IND + lane * 4;
            float s = 0.f, s2 = 0.f;
            #pragma unroll
            for (int i = 0; i < 8; i++) {
                float4 v = *(const float4*)(p + i * 128);
                s += (v.x + v.y) + (v.z + v.w);
                s2 = fmaf(v.x, v.x, s2); s2 = fmaf(v.y, v.y, s2);
                s2 = fmaf(v.z, v.z, s2); s2 = fmaf(v.w, v.w, s2);
            }
            s  = warp_sum(s);
            s2 = warp_sum(s2);
            if (lane == 0) {
                float mu  = s * (1.f / IND);
                float var = s2 * (1.f / IND) - mu * mu;
                g_mu[row] = mu;
                g_rs[row] = rsqrtf(var + 1e-5f);
            }
        }
    }

    __shared__ __align__(16) float xs[2][64];
    __shared__ __align__(16) float eqs[2][64], eks[2][64];
    __shared__ __align__(16) float beta_s[2][4];

    // register-resident fast weights as packed f32x2 pairs (16 each)
    ull wy2[16], wq2[16], wk2[16];
    {
        const int base = hd * 4096 + r * 64 + cb;   // 16B-aligned
        const ulonglong2* py = (const ulonglong2*)(Wy0 + base);
        const ulonglong2* pq = (const ulonglong2*)(Wq0 + base);
        const ulonglong2* pk = (const ulonglong2*)(Wk0 + base);
        #pragma unroll
        for (int j = 0; j < 8; j++) {
            ulonglong2 vy = py[j]; wy2[2*j] = vy.x; wy2[2*j+1] = vy.y;
            ulonglong2 vq = pq[j]; wq2[2*j] = vq.x; wq2[2*j+1] = vq.y;
            ulonglong2 vk = pk[j]; wk2[2*j] = vk.x; wk2[2*j+1] = vk.y;
        }
    }
    // wb column c, segmented: wbr[jj] packs wb[cb+2jj][c], wb[cb+2jj+1][c]
    ull wbr[16];
    {
        const float* wbp = wb0 + hd * 256 + warp;   // (j,c) stride 4
        #pragma unroll
        for (int jj = 0; jj < 16; jj++)
            wbr[jj] = pack2(wbp[(cb + 2*jj) * 4], wbp[(cb + 2*jj + 1) * 4]);
    }

    const float* hp = h    + (size_t)b * IND + hd * 64;
    float*       yp = g_ys + (size_t)b * IND + hd * 64;
    const int    stride = BSZ * IND;

    // preload x[0]; prefetch x[1] into regs
    if (tid < 64) xs[0][tid] = hp[tid];
    float nx = (tid < 64) ? __ldg(hp + stride + tid) : 0.f;
    __syncthreads();

    for (int t = 0; t < SLEN; ++t) {
        const int p  = t & 1;
        const int pn = p ^ 1;

        // ================= Phase A (reads xs[p]) =================
        ull ayA = 0ull, ayB = 0ull, aqA = 0ull, aqB = 0ull, akA = 0ull, akB = 0ull;
        ull pbA = 0ull, pbB = 0ull;
        #pragma unroll
        for (int j = 0; j < 8; j++) {
            ull x2a = *(const ull*)&xs[p][cb + 2*j];
            ull x2b = *(const ull*)&xs[p][cb + 16 + 2*j];
            ayA = ffma2(wy2[j], x2a, ayA);  ayB = ffma2(wy2[j+8], x2b, ayB);
            aqA = ffma2(wq2[j], x2a, aqA);  aqB = ffma2(wq2[j+8], x2b, aqB);
            akA = ffma2(wk2[j], x2a, akA);  akB = ffma2(wk2[j+8], x2b, akB);
            pbA = ffma2(wbr[j], x2a, pbA);  pbB = ffma2(wbr[j+8], x2b, pbB);
        }
        ull ay = fadd2(ayA, ayB), aq = fadd2(aqA, aqB), ak = fadd2(akA, akB);
        float zy, zq, zk, hi_;
        unpack2(aq, zq, hi_); zq += hi_;
        unpack2(ak, zk, hi_); zk += hi_;
        unpack2(ay, zy, hi_); zy += hi_;
        float pb;
        unpack2(fadd2(pbA, pbB), pb, hi_); pb += hi_;
        // partner lane (same row, other half): single shfl completes sums
        zq += __shfl_xor_sync(0xffffffffu, zq, 1);
        zk += __shfl_xor_sync(0xffffffffu, zk, 1);
        zy += __shfl_xor_sync(0xffffffffu, zy, 1);
        pb += __shfl_xor_sync(0xffffffffu, pb, 1);

        float eq = __expf(zq), ek = __expf(zk);
        // publish everything the barrier gates FIRST
        if (hf == 0) { eqs[p][r] = eq; eks[p][r] = ek; }
        if (lane == 0) beta_s[p][warp] = __fdividef(1.f, 1.f + __expf(-pb));
        if (tid < 64 && t + 1 < SLEN) xs[pn][tid] = nx;   // publish x[t+1]
        // y store (global, fire-and-forget) off the barrier path
        if (hf == 0) yp[(size_t)t * stride + r] = zy;
        __syncthreads();   // single barrier per step

        // ============ Phase B (reads bank p once, writes regs only) ============
        if (tid < 64 && t + 2 < SLEN) nx = __ldg(hp + (size_t)(t + 2) * stride + tid);

        // single pass: load all numerator pairs into regs, sum on the fly
        ull eq2[16], ek2[16];
        ull sq2 = 0ull, sk2 = 0ull;
        #pragma unroll
        for (int j = 0; j < 8; j++) {
            eq2[j]   = *(const ull*)&eqs[p][cb + 2*j];
            ek2[j]   = *(const ull*)&eks[p][cb + 2*j];
            eq2[j+8] = *(const ull*)&eqs[p][cb + 16 + 2*j];
            ek2[j+8] = *(const ull*)&eks[p][cb + 16 + 2*j];
            sq2 = fadd2(sq2, fadd2(eq2[j], eq2[j+8]));
            sk2 = fadd2(sk2, fadd2(ek2[j], ek2[j+8]));
        }
        float stq, stk;
        unpack2(sq2, stq, hi_); stq += hi_;
        unpack2(sk2, stk, hi_); stk += hi_;
        stq += __shfl_xor_sync(0xffffffffu, stq, 1);
        stk += __shfl_xor_sync(0xffffffffu, stk, 1);
        float invq = __fdividef(1.f, stq);
        float invk = __fdividef(1.f, stk);
        ull invq2  = pack2(invq, invq);
        ull invk2  = pack2(invk, invk);
        ull ninvk2 = pack2(-invk, -invk);

        // betas (computed in phase A, shared via smem)
        float be0 = beta_s[p][0], be1 = beta_s[p][1];
        float be2 = beta_s[p][2], be3 = beta_s[p][3];

        // dv = W (q-k) and dvb_c = wb[:,c].(q-k), all from cached numerators
        ull dyA = 0ull, dyB = 0ull, dqA = 0ull, dqB = 0ull, dkA = 0ull, dkB = 0ull;
        ull dbA = 0ull, dbB = 0ull;
        #pragma unroll
        for (int j = 0; j < 8; j++) {
            ull mka = ffma2(ek2[j],   ninvk2, fmul2(eq2[j],   invq2));
            ull mkb = ffma2(ek2[j+8], ninvk2, fmul2(eq2[j+8], invq2));
            dyA = ffma2(wy2[j], mka, dyA);  dyB = ffma2(wy2[j+8], mkb, dyB);
            dqA = ffma2(wq2[j], mka, dqA);  dqB = ffma2(wq2[j+8], mkb, dqB);
            dkA = ffma2(wk2[j], mka, dkA);  dkB = ffma2(wk2[j+8], mkb, dkB);
            dbA = ffma2(wbr[j], mka, dbA);  dbB = ffma2(wbr[j+8], mkb, dbB);
        }
        ull dy2 = fadd2(dyA, dyB), dq2 = fadd2(dqA, dqB), dk2 = fadd2(dkA, dkB);
        float dy, dq, dk, pd;
        unpack2(dy2, dy, hi_); dy += hi_;
        unpack2(dq2, dq, hi_); dq += hi_;
        unpack2(dk2, dk, hi_); dk += hi_;
        unpack2(fadd2(dbA, dbB), pd, hi_); pd += hi_;
        dy += __shfl_xor_sync(0xffffffffu, dy, 1);
        dq += __shfl_xor_sync(0xffffffffu, dq, 1);
        dk += __shfl_xor_sync(0xffffffffu, dk, 1);
        pd += __shfl_xor_sync(0xffffffffu, pd, 1);

        // rank-1 updates: W += beta*dv k^T ; wb[:,c] += be3*dvb_c k
        float a0 = be0 * dy, a1 = be1 * dq, a2 = be2 * dk, a3 = be3 * pd;
        ull a02 = pack2(a0, a0), a12 = pack2(a1, a1);
        ull a22 = pack2(a2, a2), a32 = pack2(a3, a3);
        #pragma unroll
        for (int j = 0; j < 16; j++) {
            ull kv2 = fmul2(ek2[j], invk2);
            wy2[j] = ffma2(a02, kv2, wy2[j]);
            wq2[j] = ffma2(a12, kv2, wq2[j]);
            wk2[j] = ffma2(a22, kv2, wk2[j]);
            wbr[j] = ffma2(a32, kv2, wbr[j]);
        }
        // no trailing barrier: next phase A reads xs[pn] (covered by the
        // barrier above) and writes only smem bank pn.
    }
}

// ============================================================
// Kernel 2: out = LN(h) + ys @ out_w^T via bf16-split tensor cores.
// Inputs are fp32 (g_ys, out_w); the hi/lo bf16 split happens IN
// the staging path (hidden under the mma pipeline). Dynamic smem
// double-buffer (80KB), one barrier per k-tile.
// C = Ahi*Bhi + Ahi*Blo + Alo*Bhi, fp32 accum (mma.m16n8k16.bf16).
// ============================================================
#define GEMM_SMEM_BYTES (8 * 128 * 40 * 2)   /* 81920 */

__global__ __launch_bounds__(256, 1) void out_gemm_ln_kernel(
    const float* __restrict__ h, const float* __restrict__ W,
    const float* __restrict__ gamma, const float* __restrict__ lbeta,
    float* __restrict__ out)
{
    extern __shared__ __align__(16) unsigned short smem_g[];
    // layout: [Ahi|Alo|Bhi|Blo], each 2 buffers x 5120 ushorts
    unsigned short* sAhi = smem_g;
    unsigned short* sAlo = smem_g + 2 * 5120;
    unsigned short* sBhi = smem_g + 4 * 5120;
    unsigned short* sBlo = smem_g + 6 * 5120;

    const int tid  = threadIdx.x;
    const int warp = tid >> 5, lane = tid & 31;
    const int wm = (warp >> 1) * 32, wn = (warp & 1) * 64;
    const int m0 = blockIdx.y * 128, n0 = blockIdx.x * 128;

    // staging: thread -> row (0..127), k half (0 or 16)
    const int srow = tid >> 1, skg = (tid & 1) * 16;

    float acc[2][8][4];
    #pragma unroll
    for (int i = 0; i < 2; i++)
        #pragma unroll
        for (int j = 0; j < 8; j++)
            #pragma unroll
            for (int k = 0; k < 4; k++) acc[i][j][k] = 0.f;

    const float* Af = g_ys + (size_t)(m0 + srow) * IND + skg;
    const float* Bf = W    + (size_t)(n0 + srow) * IND + skg;

    float4 fa0 = *(const float4*)(Af),      fa1 = *(const float4*)(Af + 4);
    float4 fa2 = *(const float4*)(Af + 8),  fa3 = *(const float4*)(Af + 12);
    float4 fb0 = *(const float4*)(Bf),      fb1 = *(const float4*)(Bf + 4);
    float4 fb2 = *(const float4*)(Bf + 8),  fb3 = *(const float4*)(Bf + 12);

    const int lr = lane & 15, lc = lane >> 4;
    const uint32 aHiB = smaddr(sAhi), aLoB = smaddr(sAlo);
    const uint32 bHiB = smaddr(sBhi), bLoB = smaddr(sBlo);
    const int sts = srow * 40 + skg;

    for (int kt = 0; kt < IND / 32; ++kt) {
        const int bofs = (kt & 1) * 5120;             // ushort offset
        {   // split-and-stage (conversion folded into staging)
            uint4 h0, l0, h1, l1;
            split8(fa0, fa1, h0, l0); split8(fa2, fa3, h1, l1);
            *(uint4*)(sAhi + bofs + sts) = h0;  *(uint4*)(sAhi + bofs + sts + 8) = h1;
            *(uint4*)(sAlo + bofs + sts) = l0;  *(uint4*)(sAlo + bofs + sts + 8) = l1;
            split8(fb0, fb1, h0, l0); split8(fb2, fb3, h1, l1);
            *(uint4*)(sBhi + bofs + sts) = h0;  *(uint4*)(sBhi + bofs + sts + 8) = h1;
            *(uint4*)(sBlo + bofs + sts) = l0;  *(uint4*)(sBlo + bofs + sts + 8) = l1;
        }
        __syncthreads();
        if (kt + 1 < IND / 32) {
            const int o = (kt + 1) * 32;
            fa0 = *(const float4*)(Af + o);      fa1 = *(const float4*)(Af + o + 4);
            fa2 = *(const float4*)(Af + o + 8);  fa3 = *(const float4*)(Af + o + 12);
            fb0 = *(const float4*)(Bf + o);      fb1 = *(const float4*)(Bf + o + 4);
            fb2 = *(const float4*)(Bf + o + 8);  fb3 = *(const float4*)(Bf + o + 12);
        }
        const uint32 bb = (uint32)(bofs * 2);         // byte offset of buffer
        #pragma unroll
        for (int ks = 0; ks < 2; ks++) {
            const int kb = ks * 32 + lc * 16;   // byte offset within row
            uint32 aH[2][4], aL[2][4];
            #pragma unroll
            for (int mt = 0; mt < 2; mt++) {
                uint32 off = bb + (uint32)(wm + mt * 16 + lr) * 80u + kb;
                ldmx4(aH[mt], aHiB + off);
                ldmx4(aL[mt], aLoB + off);
            }
            uint32 bH[4][4], bL[4][4];
            #pragma unroll
            for (int nc = 0; nc < 4; nc++) {
                uint32 off = bb + (uint32)(wn + nc * 16 + lr) * 80u + kb;
                ldmx4(bH[nc], bHiB + off);   // [n][k] row-major == col-major kxn
                ldmx4(bL[nc], bLoB + off);
            }
            #pragma unroll
            for (int mt = 0; mt < 2; mt++)
                #pragma unroll
                for (int nc = 0; nc < 4; nc++)
                    #pragma unroll
                    for (int hn = 0; hn < 2; hn++) {
                        float* d = acc[mt][nc * 2 + hn];
                        mma16816(d, aH[mt], bH[nc][hn], bH[nc][hn + 2]);
                        mma16816(d, aH[mt], bL[nc][hn], bL[nc][hn + 2]);
                        mma16816(d, aL[mt], bH[nc][hn], bH[nc][hn + 2]);
                    }
        }
        // next iter stores to the other buffer; reads of that buffer
        // (kt-1 compute) completed before this iteration's barrier.
    }

    // epilogue: out = acc + (h - mu) * rsig * gamma + beta
    const int g = lane >> 2, q = lane & 3;
    #pragma unroll
    for (int mt = 0; mt < 2; mt++) {
        int m1 = m0 + wm + mt * 16 + g;
        int m2 = m1 + 8;
        float mu1 = g_mu[m1], rs1 = g_rs[m1];
        float mu2 = g_mu[m2], rs2 = g_rs[m2];
        const float* h1 = h + (size_t)m1 * IND;
        const float* h2 = h + (size_t)m2 * IND;
        float* o1 = out + (size_t)m1 * IND;
        float* o2 = out + (size_t)m2 * IND;
        #pragma unroll
        for (int nt = 0; nt < 8; nt++) {
            int n = n0 + wn + (nt >> 1) * 16 + (nt & 1) * 8 + q * 2;
            float2 gm = *(const float2*)(gamma + n);
            float2 bt = *(const float2*)(lbeta + n);
            float2 hv1 = *(const float2*)(h1 + n);
            float2 hv2 = *(const float2*)(h2 + n);
            const float* d = acc[mt][nt];
            float2 r1, r2;
            r1.x = d[0] + (hv1.x - mu1) * rs1 * gm.x + bt.x;
            r1.y = d[1] + (hv1.y - mu1) * rs1 * gm.y + bt.y;
            r2.x = d[2] + (hv2.x - mu2) * rs2 * gm.x + bt.x;
            r2.y = d[3] + (hv2.y - mu2) * rs2 * gm.y + bt.y;
            *(float2*)(o1 + n) = r1;
            *(float2*)(o2 + n) = r2;
        }
    }
}

// ============================================================
extern "C" void kernel_launch(void* const* d_in, const int* in_sizes, int n_in,
                              void* d_out, int out_size) {
    const float* h   = (const float*)d_in[0];
    const float* Wy  = (const float*)d_in[1];
    const float* Wq  = (const float*)d_in[2];
    const float* Wk  = (const float*)d_in[3];
    const float* wb  = (const float*)d_in[4];
    const float* ow  = (const float*)d_in[5];
    const float* gam = (const float*)d_in[6];
    const float* bet = (const float*)d_in[7];
    float* out = (float*)d_out;

    cudaFuncSetAttribute(out_gemm_ln_kernel,
                         cudaFuncAttributeMaxDynamicSharedMemorySize,
                         GEMM_SMEM_BYTES);

    srwm_scan_kernel<<<BSZ * NH, 128>>>(h, Wy, Wq, Wk, wb);
    out_gemm_ln_kernel<<<dim3(IND / 128, ROWS / 128), 256, GEMM_SMEM_BYTES>>>(h, ow, gam, bet, out);
}